// round 1
// baseline (speedup 1.0000x reference)
#include <cuda_runtime.h>

namespace {

constexpr int NC  = 64;    // coarse samples
constexpr int NF  = 64;    // fine samples
constexpr int NA  = 128;   // total samples in fine pass
constexpr int HID = 128;
constexpr int WPB = 8;     // warps (rays) per block

struct alignas(16) WarpSh {
    float2 ab[HID];    // (o@W1 + b1, d@W1) per hidden unit : 1024 B
    float  cdf[68];    // 65 used, padded for alignment     : 272 B
    float  zall[NA];   // coarse[0:64] + fine[64:128]       : 512 B
    float  zsort[NA];  // merged sorted samples             : 512 B
};

// MLP + alpha compositing for K samples/lane (samples ordered lane-major:
// lane l owns global samples K*l .. K*l+K-1, which must be depth-sorted).
// Returns (rgb.x, rgb.y, rgb.z, depth) summed over the warp (valid on all lanes).
// If w_out != nullptr, per-sample compositing weights are written there.
template <int K>
__device__ __forceinline__ float4 composite_pass(
    const float2* __restrict__ ab, const float4* __restrict__ W2s,
    float4 b2v, const float* z, const float* delta, float* w_out, int lane)
{
    float4 acc[K];
#pragma unroll
    for (int i = 0; i < K; i++) acc[i] = b2v;

#pragma unroll 8
    for (int j = 0; j < HID; j++) {
        float2 abv = ab[j];     // broadcast LDS.64
        float4 w2  = W2s[j];    // broadcast LDS.128
#pragma unroll
        for (int i = 0; i < K; i++) {
            float h = fmaxf(fmaf(z[i], abv.y, abv.x), 0.0f);
            acc[i].x = fmaf(h, w2.x, acc[i].x);
            acc[i].y = fmaf(h, w2.y, acc[i].y);
            acc[i].z = fmaf(h, w2.z, acc[i].z);
            acc[i].w = fmaf(h, w2.w, acc[i].w);
        }
    }

    // alpha_i = 1 - exp(-delta_i * relu(sigma_i)); transmittance factors
    float alpha[K], f[K];
    float p = 1.0f;
#pragma unroll
    for (int i = 0; i < K; i++) {
        float sig = fmaxf(acc[i].w, 0.0f);
        alpha[i] = 1.0f - __expf(-delta[i] * sig);
        f[i] = 1.0f - alpha[i] + 1e-10f;
        p *= f[i];
    }

    // exclusive warp prefix-product of per-lane factor products -> T at first lane sample
    float sc = p;
#pragma unroll
    for (int off = 1; off < 32; off <<= 1) {
        float v = __shfl_up_sync(0xffffffffu, sc, off);
        if (lane >= off) sc *= v;
    }
    float T = __shfl_up_sync(0xffffffffu, sc, 1);
    if (lane == 0) T = 1.0f;

    float rx = 0.f, ry = 0.f, rz = 0.f, dd = 0.f;
#pragma unroll
    for (int i = 0; i < K; i++) {
        float w = alpha[i] * T;
        if (w_out) w_out[i] = w;
        rx = fmaf(w, acc[i].x, rx);
        ry = fmaf(w, acc[i].y, ry);
        rz = fmaf(w, acc[i].z, rz);
        dd = fmaf(w, z[i],     dd);
        T *= f[i];
    }
#pragma unroll
    for (int off = 16; off > 0; off >>= 1) {
        rx += __shfl_xor_sync(0xffffffffu, rx, off);
        ry += __shfl_xor_sync(0xffffffffu, ry, off);
        rz += __shfl_xor_sync(0xffffffffu, rz, off);
        dd += __shfl_xor_sync(0xffffffffu, dd, off);
    }
    return make_float4(rx, ry, rz, dd);
}

} // namespace

__global__ void __launch_bounds__(WPB * 32)
nerf_kernel(const float* __restrict__ rays,
            const float* __restrict__ u_coarse,
            const float* __restrict__ u_fine,
            const float* __restrict__ u_jitter,
            const float* __restrict__ W1,   // (3, 128) row-major
            const float* __restrict__ b1,   // (128,)
            const float* __restrict__ W2,   // (128, 4) row-major
            const float* __restrict__ b2,   // (4,)
            float* __restrict__ out)        // (R, 8)
{
    __shared__ float4 W2s[HID];
    __shared__ float4 b2s;
    __shared__ WarpSh wsall[WPB];

    const int tid  = threadIdx.x;
    const int wid  = tid >> 5;
    const int lane = tid & 31;
    const int ray  = blockIdx.x * WPB + wid;

    if (tid < HID) W2s[tid] = reinterpret_cast<const float4*>(W2)[tid];
    if (tid == HID) b2s = *reinterpret_cast<const float4*>(b2);
    __syncthreads();

    WarpSh& ws = wsall[wid];
    const float* rp = rays + ray * 8;   // broadcast loads
    const float ox = rp[0], oy = rp[1], oz = rp[2];
    const float dx = rp[3], dy = rp[4], dz = rp[5];
    const float nearv = rp[6], farv = rp[7];

    // Per-ray layer-1 projection: a = o@W1 + b1, bd = d@W1 (4 hidden units/lane)
#pragma unroll
    for (int i = 0; i < 4; i++) {
        int j = lane + 32 * i;
        float w0 = W1[j], w1 = W1[HID + j], w2 = W1[2 * HID + j];
        float a  = fmaf(ox, w0, fmaf(oy, w1, fmaf(oz, w2, b1[j])));
        float bd = fmaf(dx, w0, fmaf(dy, w1, dz * w2));
        ws.ab[j] = make_float2(a, bd);
    }
    __syncwarp();
    const float4 b2v = b2s;

    // ---------------- Coarse pass: samples 2*lane, 2*lane+1 ----------------
    float zc[2], dc[2];
    {
        float2 uc = reinterpret_cast<const float2*>(u_coarse + ray * NC)[lane];
        float t0 = ((float)(2 * lane)     + uc.x) * (1.0f / NC);
        float t1 = ((float)(2 * lane + 1) + uc.y) * (1.0f / NC);
        zc[0] = nearv * (1.0f - t0) + farv * t0;
        zc[1] = nearv * (1.0f - t1) + farv * t1;
        float znxt = __shfl_down_sync(0xffffffffu, zc[0], 1);
        if (lane == 31) znxt = farv;
        dc[0] = zc[1] - zc[0];
        dc[1] = znxt - zc[1];
    }
    float wgt[2];
    float4 coarse = composite_pass<2>(ws.ab, W2s, b2v, zc, dc, wgt, lane);

    // ---------------- PDF / CDF over coarse weights ----------------
    {
        float p0 = wgt[0] + 1e-5f;
        float p1 = wgt[1] + 1e-5f;
        float tot = p0 + p1;
#pragma unroll
        for (int off = 16; off > 0; off >>= 1)
            tot += __shfl_xor_sync(0xffffffffu, tot, off);
        float inv  = 1.0f / tot;
        float pdf0 = p0 * inv, pdf1 = p1 * inv;
        float sc = pdf0 + pdf1;
#pragma unroll
        for (int off = 1; off < 32; off <<= 1) {
            float v = __shfl_up_sync(0xffffffffu, sc, off);
            if (lane >= off) sc += v;
        }
        float excl = __shfl_up_sync(0xffffffffu, sc, 1);
        if (lane == 0) excl = 0.0f;
        float c1 = excl + pdf0;
        float c2 = c1 + pdf1;
        if (lane == 0) ws.cdf[0] = 0.0f;
        ws.cdf[2 * lane + 1] = c1;
        ws.cdf[2 * lane + 2] = c2;
        ws.zall[2 * lane]     = zc[0];
        ws.zall[2 * lane + 1] = zc[1];
    }
    __syncwarp();

    // ---------------- Fine sampling (searchsorted right, ind-1, jitter) ----------------
    {
        float2 uf = reinterpret_cast<const float2*>(u_fine   + ray * NF)[lane];
        float2 uj = reinterpret_cast<const float2*>(u_jitter + ray * NF)[lane];
        float us[2] = {uf.x, uf.y};
        float js[2] = {uj.x, uj.y};
#pragma unroll
        for (int k = 0; k < 2; k++) {
            // lo = count of cdf entries <= u  (= searchsorted side='right')
            int lo = 0, hi = 65;
            while (lo < hi) {
                int mid = (lo + hi) >> 1;
                if (ws.cdf[mid] <= us[k]) lo = mid + 1; else hi = mid;
            }
            float ind = fmaxf((float)lo - 1.0f, 0.0f);
            float t = (ind + js[k]) * (1.0f / NC);
            ws.zall[NC + 2 * lane + k] = nearv * (1.0f - t) + farv * t;
        }
    }
    __syncwarp();

    // ---------------- Rank-sort the 128 merged samples ----------------
    {
        float v[4];
        int   rk[4] = {0, 0, 0, 0};
#pragma unroll
        for (int i = 0; i < 4; i++) v[i] = ws.zall[lane + 32 * i];
#pragma unroll 4
        for (int j = 0; j < NA; j++) {
            float zj = ws.zall[j];   // broadcast
#pragma unroll
            for (int i = 0; i < 4; i++) {
                int idx = lane + 32 * i;
                rk[i] += (zj < v[i]) || (zj == v[i] && j < idx);  // stable tie-break
            }
        }
#pragma unroll
        for (int i = 0; i < 4; i++) ws.zsort[rk[i]] = v[i];
    }
    __syncwarp();

    // ---------------- Fine pass: samples 4*lane .. 4*lane+3 ----------------
    float zf[4], df[4];
    {
        float4 zq = *reinterpret_cast<const float4*>(&ws.zsort[4 * lane]);
        zf[0] = zq.x; zf[1] = zq.y; zf[2] = zq.z; zf[3] = zq.w;
        float znxt = __shfl_down_sync(0xffffffffu, zq.x, 1);
        if (lane == 31) znxt = farv;
        df[0] = zf[1] - zf[0];
        df[1] = zf[2] - zf[1];
        df[2] = zf[3] - zf[2];
        df[3] = znxt - zf[3];
    }
    float4 fine = composite_pass<4>(ws.ab, W2s, b2v, zf, df, nullptr, lane);

    if (lane == 0) {
        float4* op = reinterpret_cast<float4*>(out + ray * 8);
        op[0] = make_float4(coarse.x, coarse.y, coarse.z, coarse.w);
        op[1] = make_float4(fine.x, fine.y, fine.z, fine.w);
    }
}

extern "C" void kernel_launch(void* const* d_in, const int* in_sizes, int n_in,
                              void* d_out, int out_size)
{
    const float* rays     = (const float*)d_in[0];
    const float* u_coarse = (const float*)d_in[1];
    const float* u_fine   = (const float*)d_in[2];
    const float* u_jitter = (const float*)d_in[3];
    const float* W1       = (const float*)d_in[4];
    const float* b1       = (const float*)d_in[5];
    const float* W2       = (const float*)d_in[6];
    const float* b2       = (const float*)d_in[7];
    float* out            = (float*)d_out;

    const int R = in_sizes[0] / 8;          // 16384
    const int blocks = R / WPB;             // 2048
    nerf_kernel<<<blocks, WPB * 32>>>(rays, u_coarse, u_fine, u_jitter,
                                      W1, b1, W2, b2, out);
}

// round 2
// speedup vs baseline: 1.2285x; 1.2285x over previous
#include <cuda_runtime.h>

namespace {

constexpr int NC  = 64;    // coarse samples
constexpr int NA  = 128;   // total samples in fine pass
constexpr int HID = 128;
constexpr int WPB = 8;     // warps (rays) per block

using u64 = unsigned long long;

__device__ __forceinline__ u64 f32x2_fma(u64 a, u64 b, u64 c) {
    u64 d;
    asm("fma.rn.f32x2 %0, %1, %2, %3;" : "=l"(d) : "l"(a), "l"(b), "l"(c));
    return d;
}
__device__ __forceinline__ u64 pack2(float lo, float hi) {
    u64 d;
    asm("mov.b64 %0, {%1, %2};" : "=l"(d) : "f"(lo), "f"(hi));
    return d;
}
__device__ __forceinline__ float2 unpack2(u64 v) {
    float2 r;
    asm("mov.b64 {%0, %1}, %2;" : "=f"(r.x), "=f"(r.y) : "l"(v));
    return r;
}

struct alignas(16) WarpSh {
    float4 abd[HID];    // (a, a, b, b) per hidden unit        : 2048 B
    float  zsort[NA];   // merged sorted z                     : 512 B
    float  kc[NC];      // coarse keys (sorted by construction): 256 B
    float  kf[NC];      // fine keys                           : 256 B
    float  cdf[68];     // 65 used                             : 272 B
};

// MLP (layer1 collapsed to per-ray affine in z) + alpha compositing.
// P pairs => K = 2P samples per lane, lane-major, depth-sorted.
// Returns warp-summed (r, g, b, depth) on all lanes.
template <int P>
__device__ __forceinline__ float4 mlp_composite(
    const ulonglong2* __restrict__ abd,   // per-warp (aa, bb)
    const ulonglong2* __restrict__ w2a,   // (wx,wx | wy,wy)
    const ulonglong2* __restrict__ w2b,   // (wz,wz | ww,ww)
    u64 bxx, u64 byy, u64 bzz, u64 bww,
    const float* z, const float* delta, float* w_out, int lane)
{
    constexpr int K = 2 * P;
    u64 zz[P];
#pragma unroll
    for (int p = 0; p < P; p++) zz[p] = pack2(z[2 * p], z[2 * p + 1]);

    u64 ax[P], ay[P], az[P], aw[P];
#pragma unroll
    for (int p = 0; p < P; p++) { ax[p] = bxx; ay[p] = byy; az[p] = bzz; aw[p] = bww; }

#pragma unroll 8
    for (int j = 0; j < HID; j++) {
        ulonglong2 ab = abd[j];   // broadcast LDS.128
        ulonglong2 wa = w2a[j];   // broadcast LDS.128
        ulonglong2 wb = w2b[j];   // broadcast LDS.128
#pragma unroll
        for (int p = 0; p < P; p++) {
            u64 h = f32x2_fma(zz[p], ab.y, ab.x);
            float2 t = unpack2(h);
            h = pack2(fmaxf(t.x, 0.0f), fmaxf(t.y, 0.0f));
            ax[p] = f32x2_fma(h, wa.x, ax[p]);
            ay[p] = f32x2_fma(h, wa.y, ay[p]);
            az[p] = f32x2_fma(h, wb.x, az[p]);
            aw[p] = f32x2_fma(h, wb.y, aw[p]);
        }
    }

    // unpack to per-sample outputs
    float rr[K], gg[K], bb[K], ss[K];
#pragma unroll
    for (int p = 0; p < P; p++) {
        float2 vx = unpack2(ax[p]), vy = unpack2(ay[p]);
        float2 vz = unpack2(az[p]), vw = unpack2(aw[p]);
        rr[2*p] = vx.x; rr[2*p+1] = vx.y;
        gg[2*p] = vy.x; gg[2*p+1] = vy.y;
        bb[2*p] = vz.x; bb[2*p+1] = vz.y;
        ss[2*p] = vw.x; ss[2*p+1] = vw.y;
    }

    float alpha[K], f[K];
    float prod = 1.0f;
#pragma unroll
    for (int i = 0; i < K; i++) {
        float sig = fmaxf(ss[i], 0.0f);
        alpha[i] = 1.0f - __expf(-delta[i] * sig);
        f[i] = 1.0f - alpha[i] + 1e-10f;
        prod *= f[i];
    }

    // exclusive warp prefix-product of per-lane transmittance factors
    float sc = prod;
#pragma unroll
    for (int off = 1; off < 32; off <<= 1) {
        float v = __shfl_up_sync(0xffffffffu, sc, off);
        if (lane >= off) sc *= v;
    }
    float T = __shfl_up_sync(0xffffffffu, sc, 1);
    if (lane == 0) T = 1.0f;

    float rx = 0.f, ry = 0.f, rz = 0.f, dd = 0.f;
#pragma unroll
    for (int i = 0; i < K; i++) {
        float w = alpha[i] * T;
        if (w_out) w_out[i] = w;
        rx = fmaf(w, rr[i], rx);
        ry = fmaf(w, gg[i], ry);
        rz = fmaf(w, bb[i], rz);
        dd = fmaf(w, z[i],  dd);
        T *= f[i];
    }
#pragma unroll
    for (int off = 16; off > 0; off >>= 1) {
        rx += __shfl_xor_sync(0xffffffffu, rx, off);
        ry += __shfl_xor_sync(0xffffffffu, ry, off);
        rz += __shfl_xor_sync(0xffffffffu, rz, off);
        dd += __shfl_xor_sync(0xffffffffu, dd, off);
    }
    return make_float4(rx, ry, rz, dd);
}

} // namespace

__global__ void __launch_bounds__(WPB * 32)
nerf_kernel(const float* __restrict__ rays,
            const float* __restrict__ u_coarse,
            const float* __restrict__ u_fine,
            const float* __restrict__ u_jitter,
            const float* __restrict__ W1,   // (3, 128)
            const float* __restrict__ b1,   // (128,)
            const float* __restrict__ W2,   // (128, 4)
            const float* __restrict__ b2,   // (4,)
            float* __restrict__ out)        // (R, 8)
{
    __shared__ float4 W2d0[HID];   // (wx,wx,wy,wy)
    __shared__ float4 W2d1[HID];   // (wz,wz,ww,ww)
    __shared__ float4 b2s;
    __shared__ WarpSh wsall[WPB];

    const int tid  = threadIdx.x;
    const int wid  = tid >> 5;
    const int lane = tid & 31;
    const int ray  = blockIdx.x * WPB + wid;

    if (tid < HID) {
        float4 w = reinterpret_cast<const float4*>(W2)[tid];
        W2d0[tid] = make_float4(w.x, w.x, w.y, w.y);
        W2d1[tid] = make_float4(w.z, w.z, w.w, w.w);
    }
    if (tid == HID) b2s = *reinterpret_cast<const float4*>(b2);
    __syncthreads();

    WarpSh& ws = wsall[wid];
    const float* rp = rays + ray * 8;   // broadcast loads
    const float ox = rp[0], oy = rp[1], oz = rp[2];
    const float dx = rp[3], dy = rp[4], dz = rp[5];
    const float nearv = rp[6], farv = rp[7];
    const float zscale = (farv - nearv) * (1.0f / NC);   // z = near + key*zscale

    // Per-ray layer-1 affine coefficients: a = o@W1 + b1, b = d@W1
#pragma unroll
    for (int i = 0; i < 4; i++) {
        int j = lane + 32 * i;
        float w0 = W1[j], w1 = W1[HID + j], w2 = W1[2 * HID + j];
        float a  = fmaf(ox, w0, fmaf(oy, w1, fmaf(oz, w2, b1[j])));
        float bd = fmaf(dx, w0, fmaf(dy, w1, dz * w2));
        ws.abd[j] = make_float4(a, a, bd, bd);
    }
    __syncwarp();

    const float4 b2v = b2s;
    const u64 bxx = pack2(b2v.x, b2v.x), byy = pack2(b2v.y, b2v.y);
    const u64 bzz = pack2(b2v.z, b2v.z), bww = pack2(b2v.w, b2v.w);
    const ulonglong2* abd = reinterpret_cast<const ulonglong2*>(ws.abd);
    const ulonglong2* w2a = reinterpret_cast<const ulonglong2*>(W2d0);
    const ulonglong2* w2b = reinterpret_cast<const ulonglong2*>(W2d1);

    // ---------------- Coarse pass: keys 2*lane, 2*lane+1 ----------------
    float kc0, kc1, zc[2], dc[2];
    {
        float2 uc = reinterpret_cast<const float2*>(u_coarse + ray * NC)[lane];
        kc0 = (float)(2 * lane)     + uc.x;
        kc1 = (float)(2 * lane + 1) + uc.y;
        ws.kc[2 * lane]     = kc0;
        ws.kc[2 * lane + 1] = kc1;
        zc[0] = fmaf(kc0, zscale, nearv);
        zc[1] = fmaf(kc1, zscale, nearv);
        float znxt = __shfl_down_sync(0xffffffffu, zc[0], 1);
        if (lane == 31) znxt = farv;
        dc[0] = zc[1] - zc[0];
        dc[1] = znxt - zc[1];
    }
    float wgt[2];
    float4 coarse = mlp_composite<1>(abd, w2a, w2b, bxx, byy, bzz, bww,
                                     zc, dc, wgt, lane);

    // ---------------- PDF / CDF over coarse weights ----------------
    {
        float p0 = wgt[0] + 1e-5f;
        float p1 = wgt[1] + 1e-5f;
        float tot = p0 + p1;
#pragma unroll
        for (int off = 16; off > 0; off >>= 1)
            tot += __shfl_xor_sync(0xffffffffu, tot, off);
        float inv = 1.0f / tot;
        float pdf0 = p0 * inv, pdf1 = p1 * inv;
        float sc = pdf0 + pdf1;
#pragma unroll
        for (int off = 1; off < 32; off <<= 1) {
            float v = __shfl_up_sync(0xffffffffu, sc, off);
            if (lane >= off) sc += v;
        }
        float excl = __shfl_up_sync(0xffffffffu, sc, 1);
        if (lane == 0) excl = 0.0f;
        float c1 = excl + pdf0;
        if (lane == 0) ws.cdf[0] = 0.0f;
        ws.cdf[2 * lane + 1] = c1;
        ws.cdf[2 * lane + 2] = c1 + pdf1;
    }
    __syncwarp();

    // ------------- Fine sampling: searchsorted(right) - 1, + jitter -------------
    float kf0, kf1;
    int bin0, bin1;
    {
        float2 uf = reinterpret_cast<const float2*>(u_fine   + ray * NC)[lane];
        float2 uj = reinterpret_cast<const float2*>(u_jitter + ray * NC)[lane];
        float us[2] = {uf.x, uf.y};
        float js[2] = {uj.x, uj.y};
        int   bn[2];
        float kv[2];
#pragma unroll
        for (int k = 0; k < 2; k++) {
            int lo = 0, hi = 65;   // count of cdf entries <= u
            while (lo < hi) {
                int mid = (lo + hi) >> 1;
                if (ws.cdf[mid] <= us[k]) lo = mid + 1; else hi = mid;
            }
            int ind = max(lo - 1, 0);     // may be 64
            bn[k] = ind;
            kv[k] = (float)ind + js[k];   // key in [0, 65)
        }
        kf0 = kv[0]; kf1 = kv[1]; bin0 = bn[0]; bin1 = bn[1];
        ws.kf[2 * lane]     = kf0;
        ws.kf[2 * lane + 1] = kf1;
    }
    __syncwarp();

    // ---------------- Merge by rank (key space, coarse pre-sorted) ----------------
    {
        int posc0 = 2 * lane;          // coarse rank among coarse = own index
        int posc1 = 2 * lane + 1;
        int posf0 = 0, posf1 = 0;      // fine rank among fine (tie by index)
        const int if0 = 2 * lane, if1 = 2 * lane + 1;
#pragma unroll 4
        for (int j = 0; j < NC; j++) {
            float q = ws.kf[j];        // broadcast
            posc0 += (q < kc0);
            posc1 += (q < kc1);
            posf0 += (q < kf0) || (q == kf0 && j < if0);
            posf1 += (q < kf1) || (q == kf1 && j < if1);
        }
        // coarse entries before each fine sample: bin + (kc[bin] <= kf)
        posf0 += (bin0 >= NC) ? NC : (bin0 + (ws.kc[bin0] <= kf0));
        posf1 += (bin1 >= NC) ? NC : (bin1 + (ws.kc[bin1] <= kf1));

        ws.zsort[posc0] = fmaf(kc0, zscale, nearv);
        ws.zsort[posc1] = fmaf(kc1, zscale, nearv);
        ws.zsort[posf0] = fmaf(kf0, zscale, nearv);
        ws.zsort[posf1] = fmaf(kf1, zscale, nearv);
    }
    __syncwarp();

    // ---------------- Fine pass: samples 4*lane .. 4*lane+3 ----------------
    float zf[4], df[4];
    {
        float4 zq = *reinterpret_cast<const float4*>(&ws.zsort[4 * lane]);
        zf[0] = zq.x; zf[1] = zq.y; zf[2] = zq.z; zf[3] = zq.w;
        float znxt = __shfl_down_sync(0xffffffffu, zq.x, 1);
        if (lane == 31) znxt = farv;
        df[0] = zf[1] - zf[0];
        df[1] = zf[2] - zf[1];
        df[2] = zf[3] - zf[2];
        df[3] = znxt - zf[3];
    }
    float4 fine = mlp_composite<2>(abd, w2a, w2b, bxx, byy, bzz, bww,
                                   zf, df, nullptr, lane);

    if (lane == 0) {
        float4* op = reinterpret_cast<float4*>(out + ray * 8);
        op[0] = make_float4(coarse.x, coarse.y, coarse.z, coarse.w);
        op[1] = make_float4(fine.x, fine.y, fine.z, fine.w);
    }
}

extern "C" void kernel_launch(void* const* d_in, const int* in_sizes, int n_in,
                              void* d_out, int out_size)
{
    const float* rays     = (const float*)d_in[0];
    const float* u_coarse = (const float*)d_in[1];
    const float* u_fine   = (const float*)d_in[2];
    const float* u_jitter = (const float*)d_in[3];
    const float* W1       = (const float*)d_in[4];
    const float* b1       = (const float*)d_in[5];
    const float* W2       = (const float*)d_in[6];
    const float* b2       = (const float*)d_in[7];
    float* out            = (float*)d_out;

    const int R = in_sizes[0] / 8;          // 16384
    const int blocks = R / WPB;             // 2048
    nerf_kernel<<<blocks, WPB * 32>>>(rays, u_coarse, u_fine, u_jitter,
                                      W1, b1, W2, b2, out);
}